// round 13
// baseline (speedup 1.0000x reference)
#include <cuda_runtime.h>

#define NN 8
#define CC 640
#define HH 48
#define WW 48
#define KK 9
#define WQ 12                 // w-quads per row
#define TYB 16                // output rows per block
#define THREADS (WQ * TYB)    // 192
#define CG 8                  // channels per block (staged together)
#define SROWS (TYB + 2)       // 18 staged rows

__global__ __launch_bounds__(THREADS, 4) void dyn_conv_kernel(
    const float* __restrict__ q,
    const float* __restrict__ df,
    float* __restrict__ out,
    int tail_n4)
{
    __shared__ float qs[CG][SROWS][WW];   // 27648 B

    // ---- fused tail-zero slice ----
    if (blockIdx.y == CC / CG) {
        const int q_elems = NN * CC * HH * WW;
        float4* p = reinterpret_cast<float4*>(out + q_elems);
        const int tid    = threadIdx.y * WQ + threadIdx.x;
        const int gtid   = (blockIdx.z * gridDim.x + blockIdx.x) * THREADS + tid;
        const int stride = gridDim.x * gridDim.z * THREADS;
        for (int i = gtid; i < tail_n4; i += stride)
            p[i] = make_float4(0.f, 0.f, 0.f, 0.f);
        return;
    }

    const int tx   = threadIdx.x;                 // 0..11
    const int ty   = threadIdx.y;                 // 0..15
    const int tid  = ty * WQ + tx;
    const int h    = blockIdx.x * TYB + ty;       // this thread's output row
    const int h0m1 = blockIdx.x * TYB - 1;        // global row of staged row 0
    const int c0   = blockIdx.y * CG;
    const int n    = blockIdx.z;
    const int w4   = tx * 4;

    // ---- stage query band via cp.async (zero-fill OOB rows with src_size=0) ----
    {
        const float* qbase = q + (size_t)(n * CC + c0) * HH * WW;
#pragma unroll
        for (int it = 0; it < (CG * SROWS * WQ) / THREADS; it++) {   // 9 iters
            int i    = tid + it * THREADS;
            int ch   = i / (SROWS * WQ);
            int rem  = i - ch * (SROWS * WQ);
            int row  = rem / WQ;
            int quad = rem - row * WQ;
            int grow = h0m1 + row;
            const float* src = qbase + ((size_t)ch * HH + grow) * WW + quad * 4;
            unsigned smem_addr = (unsigned)__cvta_generic_to_shared(
                &qs[ch][row][quad * 4]);
            int srcsz = (grow >= 0 && grow < HH) ? 16 : 0;
            asm volatile("cp.async.cg.shared.global [%0], [%1], 16, %2;"
                         :: "r"(smem_addr), "l"(src), "r"(srcsz));
        }
        asm volatile("cp.async.commit_group;");
    }

    // ---- filter for this thread's fixed (h, w4..w4+3), in registers ----
    // (overlaps with in-flight cp.async)
    float fl[36];
    {
        const float4* fp = reinterpret_cast<const float4*>(
            df + ((size_t)(n * HH + h) * WW + (size_t)w4) * KK);
#pragma unroll
        for (int v = 0; v < 9; v++) {
            float4 t = fp[v];
            fl[v * 4 + 0] = t.x;
            fl[v * 4 + 1] = t.y;
            fl[v * 4 + 2] = t.z;
            fl[v * 4 + 3] = t.w;
        }
    }

    asm volatile("cp.async.wait_group 0;");
    __syncthreads();

    const bool lok = (w4 > 0);
    const bool rok = (w4 + 4 < WW);

    float* ob = out + ((size_t)(n * CC + c0) * HH + h) * WW + w4;
    const int CHS = HH * WW;

#pragma unroll
    for (int ch = 0; ch < CG; ch++) {
        float a0 = 0.f, a1 = 0.f, a2 = 0.f, a3 = 0.f;
#pragma unroll
        for (int di = 0; di < 3; di++) {
            const float* srow = &qs[ch][ty + di][0];
            float4 v = *reinterpret_cast<const float4*>(srow + w4);
            float rowv[6];
            rowv[0] = lok ? srow[w4 - 1] : 0.f;   // predicated scalar LDS
            rowv[1] = v.x; rowv[2] = v.y; rowv[3] = v.z; rowv[4] = v.w;
            rowv[5] = rok ? srow[w4 + 4] : 0.f;
#pragma unroll
            for (int dj = 0; dj < 3; dj++) {
                const int k = di * 3 + dj;
                a0 = fmaf(rowv[dj + 0], fl[0 * KK + k], a0);
                a1 = fmaf(rowv[dj + 1], fl[1 * KK + k], a1);
                a2 = fmaf(rowv[dj + 2], fl[2 * KK + k], a2);
                a3 = fmaf(rowv[dj + 3], fl[3 * KK + k], a3);
            }
        }

        float4 o;
        o.x = fmaxf(a0, 0.0f);
        o.y = fmaxf(a1, 0.0f);
        o.z = fmaxf(a2, 0.0f);
        o.w = fmaxf(a3, 0.0f);
        *reinterpret_cast<float4*>(ob + ch * CHS) = o;
    }
}

extern "C" void kernel_launch(void* const* d_in, const int* in_sizes, int n_in,
                              void* d_out, int out_size)
{
    const float* q  = (const float*)d_in[0];
    const float* df = (const float*)d_in[1];
    const int q_elems = NN * CC * HH * WW;
    if (n_in >= 2 && in_sizes[0] != q_elems) {
        const float* t = q; q = df; df = t;
    }

    float* out = (float*)d_out;

    const int tail    = out_size - q_elems;
    const int tail_n4 = (tail > 0) ? tail / 4 : 0;

    dim3 blk(WQ, TYB);                                        // 192 threads
    dim3 grd(HH / TYB, CC / CG + (tail_n4 > 0 ? 1 : 0), NN);  // 3 x 81 x 8
    dyn_conv_kernel<<<grd, blk>>>(q, df, out, tail_n4);
}